// round 1
// baseline (speedup 1.0000x reference)
#include <cuda_runtime.h>
#include <math.h>

#define BATCH 8
#define SEQ   2048
#define EDIM  768
#define DDIM  64
#define MTOT  (BATCH*SEQ)

// Scratch for Q, K, V projections (allocation-free rule: __device__ globals)
__device__ float g_q[MTOT*DDIM];
__device__ float g_k[MTOT*DDIM];
__device__ float g_v[MTOT*DDIM];

// ---------------------------------------------------------------------------
// Kernel 1: fused QKV projection.  out = X @ W + b for W in {Wq,Wk,Wv}
// grid (MTOT/64, 3), block 256.  64x64 tile, 4x4 microtile per thread, K-tile 16.
// ---------------------------------------------------------------------------
__global__ __launch_bounds__(256) void qkv_kernel(
    const float* __restrict__ X,
    const float* __restrict__ Wq, const float* __restrict__ bq,
    const float* __restrict__ Wk, const float* __restrict__ bk,
    const float* __restrict__ Wv, const float* __restrict__ bv)
{
    __shared__ float Xs[16][68];   // [k][row] transposed, padded
    __shared__ float Ws[16][64];   // [k][col]

    const int which = blockIdx.y;
    const float* __restrict__ W    = (which == 0) ? Wq : (which == 1) ? Wk : Wv;
    const float* __restrict__ bias = (which == 0) ? bq : (which == 1) ? bk : bv;
    float* __restrict__ out        = (which == 0) ? g_q : (which == 1) ? g_k : g_v;

    const int r0  = blockIdx.x * 64;
    const int tid = threadIdx.x;
    const int ty  = tid >> 4;      // 0..15
    const int tx  = tid & 15;      // 0..15

    // loader indices
    const int lrow = tid >> 2;     // 0..63 (X row)
    const int lkq  = tid & 3;      // 0..3  (k-quad within 16)
    const int wk   = tid >> 4;     // 0..15 (W k)
    const int wc4  = tid & 15;     // 0..15 (W col quad)

    float acc[4][4];
    #pragma unroll
    for (int i = 0; i < 4; i++)
        #pragma unroll
        for (int j = 0; j < 4; j++) acc[i][j] = 0.f;

    for (int kt = 0; kt < EDIM; kt += 16) {
        float4 xv = *reinterpret_cast<const float4*>(
            &X[(size_t)(r0 + lrow) * EDIM + kt + lkq * 4]);
        float4 wv = *reinterpret_cast<const float4*>(
            &W[(size_t)(kt + wk) * DDIM + wc4 * 4]);
        __syncthreads();
        Xs[lkq*4+0][lrow] = xv.x;
        Xs[lkq*4+1][lrow] = xv.y;
        Xs[lkq*4+2][lrow] = xv.z;
        Xs[lkq*4+3][lrow] = xv.w;
        *reinterpret_cast<float4*>(&Ws[wk][wc4*4]) = wv;
        __syncthreads();

        #pragma unroll
        for (int kk = 0; kk < 16; kk++) {
            float4 a = *reinterpret_cast<const float4*>(&Xs[kk][ty*4]);
            float4 b = *reinterpret_cast<const float4*>(&Ws[kk][tx*4]);
            float av[4] = {a.x, a.y, a.z, a.w};
            float bv2[4] = {b.x, b.y, b.z, b.w};
            #pragma unroll
            for (int i = 0; i < 4; i++)
                #pragma unroll
                for (int j = 0; j < 4; j++)
                    acc[i][j] += av[i] * bv2[j];
        }
    }

    float bj[4];
    #pragma unroll
    for (int j = 0; j < 4; j++) bj[j] = bias[tx*4 + j];

    #pragma unroll
    for (int i = 0; i < 4; i++) {
        int row = r0 + ty*4 + i;
        float4 r = make_float4(acc[i][0] + bj[0], acc[i][1] + bj[1],
                               acc[i][2] + bj[2], acc[i][3] + bj[3]);
        *reinterpret_cast<float4*>(&out[(size_t)row * DDIM + tx*4]) = r;
    }
}

// ---------------------------------------------------------------------------
// Kernel 2: flash attention.  grid (SEQ/64, BATCH), block 256.
// Per block: 64 queries x D=64. Loop over 32 key tiles of 64, online softmax.
// Thread (ty,tx): rows ty*4+i, cols tx*4+j (cols = keys in GEMM1, dims in GEMM2).
// ---------------------------------------------------------------------------
#define SM_STRIDE 68
#define ATTN_SMEM (4 * 64 * SM_STRIDE * 4)   // Qs,Ks,Vs,Ps = 69632 B

__global__ __launch_bounds__(256) void attn_kernel(float* __restrict__ out)
{
    extern __shared__ float sm[];
    float (*Qs)[SM_STRIDE] = (float(*)[SM_STRIDE])(sm);                 // [d][row]
    float (*Ks)[SM_STRIDE] = (float(*)[SM_STRIDE])(sm + 64*SM_STRIDE); // [d][key]
    float (*Vs)[SM_STRIDE] = (float(*)[SM_STRIDE])(sm + 2*64*SM_STRIDE); // [key][d]
    float (*Ps)[SM_STRIDE] = (float(*)[SM_STRIDE])(sm + 3*64*SM_STRIDE); // [key][row]

    const int b   = blockIdx.y;
    const int q0  = blockIdx.x * 64;
    const int tid = threadIdx.x;
    const int ty  = tid >> 4;
    const int tx  = tid & 15;

    const float scale = 0.125f;   // 1/sqrt(64), folded into Q at load

    // Load Q tile transposed (scaled)
    #pragma unroll
    for (int i = 0; i < 4; i++) {
        int idx4 = tid + i*256;
        int row  = idx4 >> 4;
        int dq   = idx4 & 15;
        float4 v = *reinterpret_cast<const float4*>(
            &g_q[(size_t)(b*SEQ + q0 + row) * DDIM + dq*4]);
        Qs[dq*4+0][row] = v.x * scale;
        Qs[dq*4+1][row] = v.y * scale;
        Qs[dq*4+2][row] = v.z * scale;
        Qs[dq*4+3][row] = v.w * scale;
    }

    float m[4], l[4], o[4][4];
    #pragma unroll
    for (int i = 0; i < 4; i++) {
        m[i] = -INFINITY; l[i] = 0.f;
        #pragma unroll
        for (int j = 0; j < 4; j++) o[i][j] = 0.f;
    }

    for (int kt = 0; kt < SEQ; kt += 64) {
        __syncthreads();   // prev GEMM2 done before overwriting K/V
        // Load K (transposed) and V (natural) tiles
        #pragma unroll
        for (int i = 0; i < 4; i++) {
            int idx4 = tid + i*256;
            int key  = idx4 >> 4;
            int dq   = idx4 & 15;
            size_t gofs = (size_t)(b*SEQ + kt + key) * DDIM + dq*4;
            float4 kv = *reinterpret_cast<const float4*>(&g_k[gofs]);
            float4 vv = *reinterpret_cast<const float4*>(&g_v[gofs]);
            Ks[dq*4+0][key] = kv.x;
            Ks[dq*4+1][key] = kv.y;
            Ks[dq*4+2][key] = kv.z;
            Ks[dq*4+3][key] = kv.w;
            *reinterpret_cast<float4*>(&Vs[key][dq*4]) = vv;
        }
        __syncthreads();

        // GEMM1: s[i][j] = sum_d Qs[d][row_i] * Ks[d][key_j]   (Q pre-scaled)
        float s[4][4];
        #pragma unroll
        for (int i = 0; i < 4; i++)
            #pragma unroll
            for (int j = 0; j < 4; j++) s[i][j] = 0.f;

        #pragma unroll
        for (int d = 0; d < 64; d++) {
            float4 a  = *reinterpret_cast<const float4*>(&Qs[d][ty*4]);
            float4 bb = *reinterpret_cast<const float4*>(&Ks[d][tx*4]);
            float av[4] = {a.x, a.y, a.z, a.w};
            float bv2[4] = {bb.x, bb.y, bb.z, bb.w};
            #pragma unroll
            for (int i = 0; i < 4; i++)
                #pragma unroll
                for (int j = 0; j < 4; j++)
                    s[i][j] += av[i] * bv2[j];
        }

        // Online softmax (row groups of 16 lanes; xor 1,2,4,8 stays in-group)
        float p[4][4];
        #pragma unroll
        for (int i = 0; i < 4; i++) {
            float rm = fmaxf(fmaxf(s[i][0], s[i][1]), fmaxf(s[i][2], s[i][3]));
            #pragma unroll
            for (int off = 8; off >= 1; off >>= 1)
                rm = fmaxf(rm, __shfl_xor_sync(0xffffffffu, rm, off));
            float mn = fmaxf(m[i], rm);
            float c  = __expf(m[i] - mn);
            float rs = 0.f;
            #pragma unroll
            for (int j = 0; j < 4; j++) {
                p[i][j] = __expf(s[i][j] - mn);
                rs += p[i][j];
            }
            #pragma unroll
            for (int off = 8; off >= 1; off >>= 1)
                rs += __shfl_xor_sync(0xffffffffu, rs, off);
            l[i] = l[i] * c + rs;
            m[i] = mn;
            #pragma unroll
            for (int j = 0; j < 4; j++) o[i][j] *= c;
        }

        // Store P transposed: Ps[key][row], float4 over rows
        #pragma unroll
        for (int j = 0; j < 4; j++) {
            float4 pv = make_float4(p[0][j], p[1][j], p[2][j], p[3][j]);
            *reinterpret_cast<float4*>(&Ps[tx*4+j][ty*4]) = pv;
        }
        __syncthreads();

        // GEMM2: o[i][j] += sum_k Ps[k][row_i] * Vs[k][dim_j]
        #pragma unroll
        for (int k = 0; k < 64; k++) {
            float4 a  = *reinterpret_cast<const float4*>(&Ps[k][ty*4]);
            float4 bb = *reinterpret_cast<const float4*>(&Vs[k][tx*4]);
            float av[4] = {a.x, a.y, a.z, a.w};
            float bv2[4] = {bb.x, bb.y, bb.z, bb.w};
            #pragma unroll
            for (int i = 0; i < 4; i++)
                #pragma unroll
                for (int j = 0; j < 4; j++)
                    o[i][j] += av[i] * bv2[j];
        }
    }

    // Epilogue: normalize and write out
    #pragma unroll
    for (int i = 0; i < 4; i++) {
        float inv = 1.f / l[i];
        int row = b*SEQ + q0 + ty*4 + i;
        float4 r = make_float4(o[i][0]*inv, o[i][1]*inv, o[i][2]*inv, o[i][3]*inv);
        *reinterpret_cast<float4*>(&out[(size_t)row * DDIM + tx*4]) = r;
    }
}

// ---------------------------------------------------------------------------
extern "C" void kernel_launch(void* const* d_in, const int* in_sizes, int n_in,
                              void* d_out, int out_size)
{
    const float* X  = (const float*)d_in[0];
    const float* Wq = (const float*)d_in[1];
    const float* bq = (const float*)d_in[2];
    const float* Wk = (const float*)d_in[3];
    const float* bk = (const float*)d_in[4];
    const float* Wv = (const float*)d_in[5];
    const float* bv = (const float*)d_in[6];
    float* out = (float*)d_out;

    cudaFuncSetAttribute(attn_kernel,
                         cudaFuncAttributeMaxDynamicSharedMemorySize, ATTN_SMEM);

    qkv_kernel<<<dim3(MTOT/64, 3), 256>>>(X, Wq, bq, Wk, bk, Wv, bv);
    attn_kernel<<<dim3(SEQ/64, BATCH), 256, ATTN_SMEM>>>(out);
}

// round 2
// speedup vs baseline: 2.0865x; 2.0865x over previous
#include <cuda_runtime.h>
#include <math.h>
#include <cstdint>
#include <cstddef>

#define BATCH 8
#define SEQ   2048
#define EDIM  768
#define DDIM  64
#define MTOT  (BATCH*SEQ)

// Scratch (allocation-free rule: __device__ globals)
__device__ float g_q[MTOT*DDIM];
__device__ float g_k[MTOT*DDIM];
__device__ float g_v[MTOT*DDIM];

// ---------------------------------------------------------------------------
// helpers
// ---------------------------------------------------------------------------
__device__ __forceinline__ uint32_t f2tf(float f) {
    uint32_t u;
    asm("cvt.rna.tf32.f32 %0, %1;" : "=r"(u) : "f"(f));
    return u;
}

// D(16x8,f32) += A(16x8,tf32,row) * B(8x8,tf32,col)
__device__ __forceinline__ void mma8(float* d,
                                     uint32_t a0, uint32_t a1, uint32_t a2, uint32_t a3,
                                     uint32_t b0, uint32_t b1) {
    asm volatile(
        "mma.sync.aligned.m16n8k8.row.col.f32.tf32.tf32.f32 "
        "{%0,%1,%2,%3},{%4,%5,%6,%7},{%8,%9},{%0,%1,%2,%3};"
        : "+f"(d[0]), "+f"(d[1]), "+f"(d[2]), "+f"(d[3])
        : "r"(a0), "r"(a1), "r"(a2), "r"(a3), "r"(b0), "r"(b1));
}

// ---------------------------------------------------------------------------
// Kernel 1: QKV projection, tf32 mma.  grid (MTOT/128, 3), block 256 (8 warps).
// Block tile M=128, N=64.  Warp w: rows 16w..16w+15, all 64 cols.
// Fragment layout (m16n8k8): lane l, g=l>>2, tq=l&3.
//   A: a0=A[g][tq] a1=A[g+8][tq] a2=A[g][tq+4] a3=A[g+8][tq+4]
//   B: b0=B[tq][g] b1=B[tq+4][g]      (B[k][n])
//   C: c0=C[g][2tq] c1=C[g][2tq+1] c2=C[g+8][2tq] c3=C[g+8][2tq+1]
// ---------------------------------------------------------------------------
__global__ __launch_bounds__(256) void qkv_mma(
    const float* __restrict__ X,
    const float* __restrict__ Wq, const float* __restrict__ bq,
    const float* __restrict__ Wk, const float* __restrict__ bk,
    const float* __restrict__ Wv, const float* __restrict__ bv)
{
    __shared__ uint32_t Xs[128][36];  // [row][k], stride 36: (36g+tq)%32 = 4g+tq distinct
    __shared__ uint32_t Ws[32][72];   // [k][n],  stride 72: (72tq+g)%32 = 8tq+g distinct

    const int which = blockIdx.y;
    const float* __restrict__ W    = (which == 0) ? Wq : (which == 1) ? Wk : Wv;
    const float* __restrict__ bias = (which == 0) ? bq : (which == 1) ? bk : bv;
    float* __restrict__ out        = (which == 0) ? g_q : (which == 1) ? g_k : g_v;

    const int r0   = blockIdx.x * 128;
    const int tid  = threadIdx.x;
    const int warp = tid >> 5;
    const int lane = tid & 31;
    const int g    = lane >> 2;
    const int tq   = lane & 3;

    float acc[8][4];
    #pragma unroll
    for (int nf = 0; nf < 8; nf++)
        #pragma unroll
        for (int j = 0; j < 4; j++) acc[nf][j] = 0.f;

    const int xr = tid >> 3, xc = (tid & 7) * 4;   // X loader: 32 rows/pass
    const int wr = tid >> 4, wc = (tid & 15) * 4;  // W loader: 16 rows/pass

    for (int kt = 0; kt < EDIM; kt += 32) {
        __syncthreads();
        #pragma unroll
        for (int i = 0; i < 4; i++) {
            float4 v = *reinterpret_cast<const float4*>(
                &X[(size_t)(r0 + xr + 32*i) * EDIM + kt + xc]);
            Xs[xr + 32*i][xc + 0] = f2tf(v.x);
            Xs[xr + 32*i][xc + 1] = f2tf(v.y);
            Xs[xr + 32*i][xc + 2] = f2tf(v.z);
            Xs[xr + 32*i][xc + 3] = f2tf(v.w);
        }
        #pragma unroll
        for (int i = 0; i < 2; i++) {
            float4 v = *reinterpret_cast<const float4*>(
                &W[(size_t)(kt + wr + 16*i) * DDIM + wc]);
            Ws[wr + 16*i][wc + 0] = f2tf(v.x);
            Ws[wr + 16*i][wc + 1] = f2tf(v.y);
            Ws[wr + 16*i][wc + 2] = f2tf(v.z);
            Ws[wr + 16*i][wc + 3] = f2tf(v.w);
        }
        __syncthreads();

        #pragma unroll
        for (int k8 = 0; k8 < 4; k8++) {
            uint32_t a0 = Xs[16*warp + g    ][k8*8 + tq    ];
            uint32_t a1 = Xs[16*warp + g + 8][k8*8 + tq    ];
            uint32_t a2 = Xs[16*warp + g    ][k8*8 + tq + 4];
            uint32_t a3 = Xs[16*warp + g + 8][k8*8 + tq + 4];
            #pragma unroll
            for (int nf = 0; nf < 8; nf++) {
                uint32_t b0 = Ws[k8*8 + tq    ][nf*8 + g];
                uint32_t b1 = Ws[k8*8 + tq + 4][nf*8 + g];
                mma8(acc[nf], a0, a1, a2, a3, b0, b1);
            }
        }
    }

    #pragma unroll
    for (int nf = 0; nf < 8; nf++) {
        int col = nf*8 + 2*tq;
        float bb0 = bias[col], bb1 = bias[col + 1];
        int row0 = r0 + 16*warp + g;
        float2 v0 = make_float2(acc[nf][0] + bb0, acc[nf][1] + bb1);
        float2 v1 = make_float2(acc[nf][2] + bb0, acc[nf][3] + bb1);
        *reinterpret_cast<float2*>(&out[(size_t)row0 * DDIM + col])       = v0;
        *reinterpret_cast<float2*>(&out[(size_t)(row0+8) * DDIM + col])   = v1;
    }
}

// ---------------------------------------------------------------------------
// Kernel 2: flash attention, tf32 mma.  grid (SEQ/64, BATCH), block 128 (4 warps).
// Warp w: query rows 16w..16w+15 (local).  Key tiles of 64.  Q frags in regs.
// P is warp-private (warp writes+reads only its own 16 Ps rows) -> no block
// syncs around GEMM2, only __syncwarp().  Softmax in base-2 (log2e in qscale).
// ---------------------------------------------------------------------------
#define ATTN_SMEM ((64*68 + 64*72 + 64*68) * 4)   // Ks + Vs + Ps = 53248 B

__global__ __launch_bounds__(128, 3) void attn_mma(float* __restrict__ out)
{
    extern __shared__ uint32_t sm2[];
    uint32_t (*Ks)[68] = (uint32_t(*)[68])(sm2);                      // [key][d]
    uint32_t (*Vs)[72] = (uint32_t(*)[72])(sm2 + 64*68);              // [key][d]
    uint32_t (*Ps)[68] = (uint32_t(*)[68])(sm2 + 64*68 + 64*72);     // [qrow][key]

    const int b    = blockIdx.y;
    const int q0   = blockIdx.x * 64;
    const int tid  = threadIdx.x;
    const int warp = tid >> 5;
    const int lane = tid & 31;
    const int g    = lane >> 2;
    const int tq   = lane & 3;

    // 1/sqrt(64) * log2(e): softmax done in base-2 domain
    const float qscale = 0.125f * 1.4426950408889634f;

    // Q fragments: rows (16w+g, 16w+g+8) x all 64 dims, resident in registers
    const size_t gQ0 = (size_t)(b*SEQ + q0 + 16*warp + g) * DDIM;
    uint32_t qa[8][4];
    #pragma unroll
    for (int k8 = 0; k8 < 8; k8++) {
        qa[k8][0] = f2tf(g_q[gQ0            + k8*8 + tq    ] * qscale);
        qa[k8][1] = f2tf(g_q[gQ0 + 8*DDIM   + k8*8 + tq    ] * qscale);
        qa[k8][2] = f2tf(g_q[gQ0            + k8*8 + tq + 4] * qscale);
        qa[k8][3] = f2tf(g_q[gQ0 + 8*DDIM   + k8*8 + tq + 4] * qscale);
    }

    float m0 = -INFINITY, m1 = -INFINITY, l0 = 0.f, l1 = 0.f;
    float o[8][4];
    #pragma unroll
    for (int nf = 0; nf < 8; nf++)
        #pragma unroll
        for (int j = 0; j < 4; j++) o[nf][j] = 0.f;

    // K/V loader: thread -> (key=tid>>1, 32-col half); warp covers 16 full rows
    const int key = tid >> 1, ch = (tid & 1) * 32;
    const size_t gKV = (size_t)(b*SEQ + key) * DDIM + ch;

    for (int kt = 0; kt < SEQ; kt += 64) {
        __syncthreads();
        #pragma unroll
        for (int i = 0; i < 8; i++) {
            float4 kv = *reinterpret_cast<const float4*>(&g_k[gKV + (size_t)kt*DDIM + i*4]);
            float4 vv = *reinterpret_cast<const float4*>(&g_v[gKV + (size_t)kt*DDIM + i*4]);
            int c = ch + i*4;
            Ks[key][c+0] = f2tf(kv.x); Ks[key][c+1] = f2tf(kv.y);
            Ks[key][c+2] = f2tf(kv.z); Ks[key][c+3] = f2tf(kv.w);
            Vs[key][c+0] = f2tf(vv.x); Vs[key][c+1] = f2tf(vv.y);
            Vs[key][c+2] = f2tf(vv.z); Vs[key][c+3] = f2tf(vv.w);
        }
        __syncthreads();

        // GEMM1: S[16 x 64keys] = Q * K^T   (B[k=d][n=key] = Ks[key][d])
        float s[8][4];
        #pragma unroll
        for (int nf = 0; nf < 8; nf++)
            #pragma unroll
            for (int j = 0; j < 4; j++) s[nf][j] = 0.f;

        #pragma unroll
        for (int k8 = 0; k8 < 8; k8++) {
            #pragma unroll
            for (int nf = 0; nf < 8; nf++) {
                uint32_t b0 = Ks[nf*8 + g][k8*8 + tq    ];
                uint32_t b1 = Ks[nf*8 + g][k8*8 + tq + 4];
                mma8(s[nf], qa[k8][0], qa[k8][1], qa[k8][2], qa[k8][3], b0, b1);
            }
        }

        // online softmax: rows g (s0,s1) and g+8 (s2,s3); quad lanes share row
        float rm0 = -INFINITY, rm1 = -INFINITY;
        #pragma unroll
        for (int nf = 0; nf < 8; nf++) {
            rm0 = fmaxf(rm0, fmaxf(s[nf][0], s[nf][1]));
            rm1 = fmaxf(rm1, fmaxf(s[nf][2], s[nf][3]));
        }
        rm0 = fmaxf(rm0, __shfl_xor_sync(0xffffffffu, rm0, 1));
        rm0 = fmaxf(rm0, __shfl_xor_sync(0xffffffffu, rm0, 2));
        rm1 = fmaxf(rm1, __shfl_xor_sync(0xffffffffu, rm1, 1));
        rm1 = fmaxf(rm1, __shfl_xor_sync(0xffffffffu, rm1, 2));

        float mn0 = fmaxf(m0, rm0), mn1 = fmaxf(m1, rm1);
        float cr0 = exp2f(m0 - mn0), cr1 = exp2f(m1 - mn1);
        float rs0 = 0.f, rs1 = 0.f;

        #pragma unroll
        for (int nf = 0; nf < 8; nf++) {
            float p0 = exp2f(s[nf][0] - mn0);
            float p1 = exp2f(s[nf][1] - mn0);
            float p2 = exp2f(s[nf][2] - mn1);
            float p3 = exp2f(s[nf][3] - mn1);
            rs0 += p0 + p1;
            rs1 += p2 + p3;
            int c = nf*8 + 2*tq;
            Ps[16*warp + g    ][c]   = f2tf(p0);
            Ps[16*warp + g    ][c+1] = f2tf(p1);
            Ps[16*warp + g + 8][c]   = f2tf(p2);
            Ps[16*warp + g + 8][c+1] = f2tf(p3);
            o[nf][0] *= cr0; o[nf][1] *= cr0;
            o[nf][2] *= cr1; o[nf][3] *= cr1;
        }
        rs0 += __shfl_xor_sync(0xffffffffu, rs0, 1);
        rs0 += __shfl_xor_sync(0xffffffffu, rs0, 2);
        rs1 += __shfl_xor_sync(0xffffffffu, rs1, 1);
        rs1 += __shfl_xor_sync(0xffffffffu, rs1, 2);
        l0 = l0 * cr0 + rs0;
        l1 = l1 * cr1 + rs1;
        m0 = mn0; m1 = mn1;
        __syncwarp();   // Ps is warp-private: warp-level visibility suffices

        // GEMM2: O[16 x 64] += P[16 x 64keys] * V[64keys x 64]
        #pragma unroll
        for (int k8 = 0; k8 < 8; k8++) {
            uint32_t a0 = Ps[16*warp + g    ][k8*8 + tq    ];
            uint32_t a1 = Ps[16*warp + g + 8][k8*8 + tq    ];
            uint32_t a2 = Ps[16*warp + g    ][k8*8 + tq + 4];
            uint32_t a3 = Ps[16*warp + g + 8][k8*8 + tq + 4];
            #pragma unroll
            for (int nf = 0; nf < 8; nf++) {
                uint32_t b0 = Vs[k8*8 + tq    ][nf*8 + g];
                uint32_t b1 = Vs[k8*8 + tq + 4][nf*8 + g];
                mma8(o[nf], a0, a1, a2, a3, b0, b1);
            }
        }
    }

    // epilogue
    float inv0 = 1.f / l0, inv1 = 1.f / l1;
    const size_t orow = (size_t)(b*SEQ + q0 + 16*warp + g) * DDIM;
    #pragma unroll
    for (int nf = 0; nf < 8; nf++) {
        int c = nf*8 + 2*tq;
        float2 v0 = make_float2(o[nf][0] * inv0, o[nf][1] * inv0);
        float2 v1 = make_float2(o[nf][2] * inv1, o[nf][3] * inv1);
        *reinterpret_cast<float2*>(&out[orow + c])            = v0;
        *reinterpret_cast<float2*>(&out[orow + 8*DDIM + c])   = v1;
    }
}

// ---------------------------------------------------------------------------
extern "C" void kernel_launch(void* const* d_in, const int* in_sizes, int n_in,
                              void* d_out, int out_size)
{
    const float* X  = (const float*)d_in[0];
    const float* Wq = (const float*)d_in[1];
    const float* bq = (const float*)d_in[2];
    const float* Wk = (const float*)d_in[3];
    const float* bk = (const float*)d_in[4];
    const float* Wv = (const float*)d_in[5];
    const float* bv = (const float*)d_in[6];
    float* out = (float*)d_out;

    cudaFuncSetAttribute(attn_mma,
                         cudaFuncAttributeMaxDynamicSharedMemorySize, ATTN_SMEM);

    qkv_mma<<<dim3(MTOT/128, 3), 256>>>(X, Wq, bq, Wk, bk, Wv, bv);
    attn_mma<<<dim3(SEQ/64, BATCH), 128, ATTN_SMEM>>>(out);
}

// round 3
// speedup vs baseline: 5.1951x; 2.4898x over previous
#include <cuda_runtime.h>
#include <cuda_fp16.h>
#include <math.h>
#include <cstdint>
#include <cstddef>

#define BATCH 8
#define SEQ   2048
#define EDIM  768
#define DDIM  64
#define MTOT  (BATCH*SEQ)

// fp16 scratch for Q (pre-scaled), K, V
__device__ __half g_q[MTOT*DDIM];
__device__ __half g_k[MTOT*DDIM];
__device__ __half g_v[MTOT*DDIM];

// ---------------------------------------------------------------------------
// helpers
// ---------------------------------------------------------------------------
__device__ __forceinline__ float ex2(float x) {
    float y; asm("ex2.approx.ftz.f32 %0, %1;" : "=f"(y) : "f"(x)); return y;
}
__device__ __forceinline__ uint32_t smaddr(const void* p) {
    return (uint32_t)__cvta_generic_to_shared(p);
}
__device__ __forceinline__ void ldsm4(uint32_t& r0, uint32_t& r1, uint32_t& r2,
                                      uint32_t& r3, uint32_t a) {
    asm volatile("ldmatrix.sync.aligned.m8n8.x4.shared.b16 {%0,%1,%2,%3}, [%4];"
                 : "=r"(r0), "=r"(r1), "=r"(r2), "=r"(r3) : "r"(a));
}
__device__ __forceinline__ void ldsm4t(uint32_t& r0, uint32_t& r1, uint32_t& r2,
                                       uint32_t& r3, uint32_t a) {
    asm volatile("ldmatrix.sync.aligned.m8n8.x4.trans.shared.b16 {%0,%1,%2,%3}, [%4];"
                 : "=r"(r0), "=r"(r1), "=r"(r2), "=r"(r3) : "r"(a));
}
// D(16x8,f32) += A(16x16,f16) * B(16x8,f16)
__device__ __forceinline__ void mma16(float* d,
                                      uint32_t a0, uint32_t a1, uint32_t a2, uint32_t a3,
                                      uint32_t b0, uint32_t b1) {
    asm volatile(
        "mma.sync.aligned.m16n8k16.row.col.f32.f16.f16.f32 "
        "{%0,%1,%2,%3},{%4,%5,%6,%7},{%8,%9},{%0,%1,%2,%3};"
        : "+f"(d[0]), "+f"(d[1]), "+f"(d[2]), "+f"(d[3])
        : "r"(a0), "r"(a1), "r"(a2), "r"(a3), "r"(b0), "r"(b1));
}
__device__ __forceinline__ void cpasync16(uint32_t dst, const void* src) {
    asm volatile("cp.async.cg.shared.global [%0], [%1], 16;" :: "r"(dst), "l"(src));
}

// ---------------------------------------------------------------------------
// Kernel 1: fused QKV projection, fp16 mma. grid (MTOT/128), block 256 (8 warps).
// Block tile: M=128 rows of X, N=192 (Q|K|V 64 each), K-tile=32. X read once.
// Warp w: rows 16w..16w+15, all 192 cols (nf = 24 n-blocks of 8).
// ---------------------------------------------------------------------------
#define XS_STRIDE 40
#define WS_STRIDE 200

__global__ __launch_bounds__(256) void qkv_mma(
    const float* __restrict__ X,
    const float* __restrict__ Wq, const float* __restrict__ bq,
    const float* __restrict__ Wk, const float* __restrict__ bk,
    const float* __restrict__ Wv, const float* __restrict__ bv)
{
    __shared__ __half Xs[128 * XS_STRIDE];   // [row][k], stride 40 halves
    __shared__ __half Ws[32 * WS_STRIDE];    // [k][n],  stride 200 halves (n=192)

    const int r0   = blockIdx.x * 128;
    const int tid  = threadIdx.x;
    const int warp = tid >> 5;
    const int lane = tid & 31;
    const int g    = lane >> 2;
    const int tq   = lane & 3;
    const int mat  = lane >> 3;   // ldmatrix matrix id
    const int mr   = lane & 7;    // ldmatrix row within matrix

    const float qscale = 0.125f * 1.4426950408889634f;  // 1/sqrt(D) * log2e

    float acc[24][4];
    #pragma unroll
    for (int nf = 0; nf < 24; nf++)
        #pragma unroll
        for (int j = 0; j < 4; j++) acc[nf][j] = 0.f;

    // loader indices
    const int xr = tid >> 3, xc = (tid & 7) * 4;    // X: 32 rows/pass, 4 passes
    const int wr = tid >> 4, wq4 = (tid & 15) * 4;  // W: 16 rows/pass, 2 passes, 3 mats

    // ldmatrix base offsets (halves)
    // A (non-trans): row = 16w + 8*(mat&1) + mr, kcol = 8*(mat>>1)
    const uint32_t a_base = smaddr(Xs) +
        ((16*warp + 8*(mat & 1) + mr) * XS_STRIDE + 8*(mat >> 1)) * 2;
    // B (trans): k = 8*(mat&1) + mr, n = 8*(mat>>1)
    const uint32_t b_base = smaddr(Ws) +
        ((8*(mat & 1) + mr) * WS_STRIDE + 8*(mat >> 1)) * 2;

    const float* Wsel[3] = {Wq, Wk, Wv};

    for (int kt = 0; kt < EDIM; kt += 32) {
        float4 xv[4], wv[6];
        #pragma unroll
        for (int i = 0; i < 4; i++)
            xv[i] = *reinterpret_cast<const float4*>(
                &X[(size_t)(r0 + xr + 32*i) * EDIM + kt + xc]);
        #pragma unroll
        for (int p = 0; p < 3; p++)
            #pragma unroll
            for (int rh = 0; rh < 2; rh++)
                wv[p*2+rh] = *reinterpret_cast<const float4*>(
                    &Wsel[p][(size_t)(kt + wr + 16*rh) * DDIM + wq4]);

        __syncthreads();
        #pragma unroll
        for (int i = 0; i < 4; i++) {
            __half2* d = reinterpret_cast<__half2*>(&Xs[(xr + 32*i) * XS_STRIDE + xc]);
            d[0] = __floats2half2_rn(xv[i].x, xv[i].y);
            d[1] = __floats2half2_rn(xv[i].z, xv[i].w);
        }
        #pragma unroll
        for (int p = 0; p < 3; p++)
            #pragma unroll
            for (int rh = 0; rh < 2; rh++) {
                float4 v = wv[p*2+rh];
                __half2* d = reinterpret_cast<__half2*>(
                    &Ws[(wr + 16*rh) * WS_STRIDE + p*64 + wq4]);
                d[0] = __floats2half2_rn(v.x, v.y);
                d[1] = __floats2half2_rn(v.z, v.w);
            }
        __syncthreads();

        #pragma unroll
        for (int k16 = 0; k16 < 2; k16++) {
            uint32_t a0, a1, a2, a3;
            ldsm4(a0, a1, a2, a3, a_base + (k16*16) * 2);
            #pragma unroll
            for (int nf2 = 0; nf2 < 24; nf2 += 2) {
                uint32_t b0, b1, b2, b3;
                ldsm4t(b0, b1, b2, b3,
                       b_base + (k16*16*WS_STRIDE + nf2*8) * 2);
                mma16(acc[nf2],   a0, a1, a2, a3, b0, b1);
                mma16(acc[nf2+1], a0, a1, a2, a3, b2, b3);
            }
        }
    }

    // epilogue: +bias, scale (q only), convert fp16, store
    const float* bsel[3] = {bq, bk, bv};
    __half* osel[3] = {g_q, g_k, g_v};
    #pragma unroll
    for (int nf = 0; nf < 24; nf++) {
        int which = nf >> 3;
        int col   = (nf & 7) * 8 + 2*tq;
        float sc  = (which == 0) ? qscale : 1.f;
        float bb0 = bsel[which][col], bb1 = bsel[which][col + 1];
        int row0 = r0 + 16*warp + g;
        __half2 v0 = __floats2half2_rn((acc[nf][0] + bb0) * sc, (acc[nf][1] + bb1) * sc);
        __half2 v1 = __floats2half2_rn((acc[nf][2] + bb0) * sc, (acc[nf][3] + bb1) * sc);
        *reinterpret_cast<__half2*>(&osel[which][(size_t)row0 * DDIM + col])     = v0;
        *reinterpret_cast<__half2*>(&osel[which][(size_t)(row0+8) * DDIM + col]) = v1;
    }
}

// ---------------------------------------------------------------------------
// Kernel 2: flash attention, fp16 mma + ldmatrix + cp.async double buffer.
// grid (SEQ/64, BATCH), block 128 (4 warps). Warp w: query rows 16w..16w+15.
// P never touches smem: S's C-fragment IS the PV GEMM's A-fragment.
// ---------------------------------------------------------------------------
#define KV_STRIDE 72
#define KVBUF (64 * KV_STRIDE)          // halves per K (or V) buffer

__global__ __launch_bounds__(128) void attn_mma(float* __restrict__ out)
{
    __shared__ __half smkv[4 * KVBUF];  // [K0][V0][K1][V1]

    const int b    = blockIdx.y;
    const int q0   = blockIdx.x * 64;
    const int tid  = threadIdx.x;
    const int warp = tid >> 5;
    const int lane = tid & 31;
    const int g    = lane >> 2;
    const int tq   = lane & 3;
    const int mat  = lane >> 3;
    const int mr   = lane & 7;

    // Q fragments from gmem (already scaled by 0.125*log2e in projection)
    const __half* qrow = g_q + (size_t)(b*SEQ + q0 + 16*warp + g) * DDIM;
    uint32_t qa[4][4];
    #pragma unroll
    for (int k16 = 0; k16 < 4; k16++) {
        qa[k16][0] = *reinterpret_cast<const uint32_t*>(qrow           + k16*16 + 2*tq);
        qa[k16][1] = *reinterpret_cast<const uint32_t*>(qrow + 8*DDIM  + k16*16 + 2*tq);
        qa[k16][2] = *reinterpret_cast<const uint32_t*>(qrow           + k16*16 + 8 + 2*tq);
        qa[k16][3] = *reinterpret_cast<const uint32_t*>(qrow + 8*DDIM  + k16*16 + 8 + 2*tq);
    }

    float m0 = -INFINITY, m1 = -INFINITY, l0 = 0.f, l1 = 0.f;
    float o[8][4];
    #pragma unroll
    for (int nf = 0; nf < 8; nf++)
        #pragma unroll
        for (int j = 0; j < 4; j++) o[nf][j] = 0.f;

    // cp.async loader: 4 chunks per array per thread; chunk c: row=c>>3, col16=c&7
    const uint32_t kv_base_sm = smaddr(smkv);
    const __half* gk = g_k + (size_t)(b*SEQ) * DDIM;
    const __half* gv = g_v + (size_t)(b*SEQ) * DDIM;

    auto issue_tile = [&](int kt, int buf) {
        uint32_t kdst = kv_base_sm + (2*buf) * KVBUF * 2;
        uint32_t vdst = kdst + KVBUF * 2;
        #pragma unroll
        for (int i = 0; i < 4; i++) {
            int c = tid + 128*i;
            int row = c >> 3, col16 = c & 7;
            uint32_t doff = (row * KV_STRIDE + col16*8) * 2;
            size_t   goff = (size_t)(kt + row) * DDIM + col16*8;
            cpasync16(kdst + doff, gk + goff);
            cpasync16(vdst + doff, gv + goff);
        }
    };

    // ldmatrix per-lane base offsets (bytes)
    // GEMM1 (non-trans on K): key = 8*(mat>>1)+mr, d = 8*(mat&1)
    const uint32_t k_off = ((8*(mat >> 1) + mr) * KV_STRIDE + 8*(mat & 1)) * 2;
    // GEMM2 (trans on V): key = 8*(mat&1)+mr, d = 8*(mat>>1)
    const uint32_t v_off = ((8*(mat & 1) + mr) * KV_STRIDE + 8*(mat >> 1)) * 2;

    issue_tile(0, 0);
    asm volatile("cp.async.commit_group;");

    for (int it = 0; it < SEQ/64; ++it) {
        const int cur = it & 1;
        if (it + 1 < SEQ/64) {
            issue_tile((it+1)*64, cur ^ 1);
            asm volatile("cp.async.commit_group;");
            asm volatile("cp.async.wait_group 1;");
        } else {
            asm volatile("cp.async.wait_group 0;");
        }
        __syncthreads();

        const uint32_t ks = kv_base_sm + (2*cur) * KVBUF * 2;
        const uint32_t vs = ks + KVBUF * 2;

        // ---- GEMM1: S[16 x 64] = Q * K^T ----
        float s[8][4];
        #pragma unroll
        for (int nf = 0; nf < 8; nf++)
            #pragma unroll
            for (int j = 0; j < 4; j++) s[nf][j] = 0.f;

        #pragma unroll
        for (int k16 = 0; k16 < 4; k16++) {
            #pragma unroll
            for (int nf2 = 0; nf2 < 8; nf2 += 2) {
                uint32_t b0, b1, b2, b3;
                ldsm4(b0, b1, b2, b3,
                      ks + k_off + (nf2*8*KV_STRIDE + k16*16) * 2);
                mma16(s[nf2],   qa[k16][0], qa[k16][1], qa[k16][2], qa[k16][3], b0, b1);
                mma16(s[nf2+1], qa[k16][0], qa[k16][1], qa[k16][2], qa[k16][3], b2, b3);
            }
        }

        // ---- online softmax (base-2 domain) ----
        float rm0 = -INFINITY, rm1 = -INFINITY;
        #pragma unroll
        for (int nf = 0; nf < 8; nf++) {
            rm0 = fmaxf(rm0, fmaxf(s[nf][0], s[nf][1]));
            rm1 = fmaxf(rm1, fmaxf(s[nf][2], s[nf][3]));
        }
        rm0 = fmaxf(rm0, __shfl_xor_sync(0xffffffffu, rm0, 1));
        rm0 = fmaxf(rm0, __shfl_xor_sync(0xffffffffu, rm0, 2));
        rm1 = fmaxf(rm1, __shfl_xor_sync(0xffffffffu, rm1, 1));
        rm1 = fmaxf(rm1, __shfl_xor_sync(0xffffffffu, rm1, 2));

        float mn0 = fmaxf(m0, rm0), mn1 = fmaxf(m1, rm1);
        float cr0 = ex2(m0 - mn0),  cr1 = ex2(m1 - mn1);
        float rs0 = 0.f, rs1 = 0.f;
        uint32_t ph0[8], ph1[8];   // P fragments: rows g / g+8, packed f16x2

        #pragma unroll
        for (int nf = 0; nf < 8; nf++) {
            float p0 = ex2(s[nf][0] - mn0);
            float p1 = ex2(s[nf][1] - mn0);
            float p2 = ex2(s[nf][2] - mn1);
            float p3 = ex2(s[nf][3] - mn1);
            rs0 += p0 + p1;  rs1 += p2 + p3;
            __half2 h0 = __floats2half2_rn(p0, p1);
            __half2 h1 = __floats2half2_rn(p2, p3);
            ph0[nf] = *reinterpret_cast<uint32_t*>(&h0);
            ph1[nf] = *reinterpret_cast<uint32_t*>(&h1);
            o[nf][0] *= cr0; o[nf][1] *= cr0;
            o[nf][2] *= cr1; o[nf][3] *= cr1;
        }
        rs0 += __shfl_xor_sync(0xffffffffu, rs0, 1);
        rs0 += __shfl_xor_sync(0xffffffffu, rs0, 2);
        rs1 += __shfl_xor_sync(0xffffffffu, rs1, 1);
        rs1 += __shfl_xor_sync(0xffffffffu, rs1, 2);
        l0 = l0 * cr0 + rs0;
        l1 = l1 * cr1 + rs1;
        m0 = mn0; m1 = mn1;

        // ---- GEMM2: O += P * V  (A-fragments = ph registers, no smem) ----
        #pragma unroll
        for (int k16 = 0; k16 < 4; k16++) {
            uint32_t pa0 = ph0[2*k16], pa1 = ph1[2*k16];
            uint32_t pa2 = ph0[2*k16+1], pa3 = ph1[2*k16+1];
            #pragma unroll
            for (int nf2 = 0; nf2 < 8; nf2 += 2) {
                uint32_t b0, b1, b2, b3;
                ldsm4t(b0, b1, b2, b3,
                       vs + v_off + (k16*16*KV_STRIDE + nf2*8) * 2);
                mma16(o[nf2],   pa0, pa1, pa2, pa3, b0, b1);
                mma16(o[nf2+1], pa0, pa1, pa2, pa3, b2, b3);
            }
        }
        __syncthreads();
    }

    // epilogue
    float inv0 = 1.f / l0, inv1 = 1.f / l1;
    const size_t orow = (size_t)(b*SEQ + q0 + 16*warp + g) * DDIM;
    #pragma unroll
    for (int nf = 0; nf < 8; nf++) {
        int c = nf*8 + 2*tq;
        *reinterpret_cast<float2*>(&out[orow + c]) =
            make_float2(o[nf][0] * inv0, o[nf][1] * inv0);
        *reinterpret_cast<float2*>(&out[orow + 8*DDIM + c]) =
            make_float2(o[nf][2] * inv1, o[nf][3] * inv1);
    }
}

// ---------------------------------------------------------------------------
extern "C" void kernel_launch(void* const* d_in, const int* in_sizes, int n_in,
                              void* d_out, int out_size)
{
    const float* X  = (const float*)d_in[0];
    const float* Wq = (const float*)d_in[1];
    const float* bq = (const float*)d_in[2];
    const float* Wk = (const float*)d_in[3];
    const float* bk = (const float*)d_in[4];
    const float* Wv = (const float*)d_in[5];
    const float* bv = (const float*)d_in[6];
    float* out = (float*)d_out;

    qkv_mma<<<dim3(MTOT/128), 256>>>(X, Wq, bq, Wk, bk, Wv, bv);
    attn_mma<<<dim3(SEQ/64, BATCH), 128>>>(out);
}